// round 12
// baseline (speedup 1.0000x reference)
#include <cuda_runtime.h>
#include <cuda_bf16.h>
#include <cstdint>

#define NN   50000
#define ECNT 800000

// ===================== helpers =============================================
__device__ __forceinline__ uint32_t smem_to_u32(const void* p) {
    uint32_t a;
    asm("{ .reg .u64 t; cvta.to.shared.u64 t, %1; cvt.u32.u64 %0, t; }"
        : "=r"(a) : "l"(p));
    return a;
}
__device__ __forceinline__ void ldsm_x4(uint32_t* r, uint32_t addr) {
    asm volatile("ldmatrix.sync.aligned.m8n8.x4.shared.b16 {%0,%1,%2,%3}, [%4];"
        : "=r"(r[0]), "=r"(r[1]), "=r"(r[2]), "=r"(r[3]) : "r"(addr));
}
__device__ __forceinline__ void mma_bf16(float* c, const uint32_t* a,
                                         uint32_t b0, uint32_t b1) {
    asm volatile("mma.sync.aligned.m16n8k16.row.col.f32.bf16.bf16.f32 "
        "{%0,%1,%2,%3}, {%4,%5,%6,%7}, {%8,%9}, {%0,%1,%2,%3};"
        : "+f"(c[0]), "+f"(c[1]), "+f"(c[2]), "+f"(c[3])
        : "r"(a[0]), "r"(a[1]), "r"(a[2]), "r"(a[3]), "r"(b0), "r"(b1));
}
__device__ __forceinline__ void cp16(uint32_t dst, const void* src) {
    asm volatile("cp.async.cg.shared.global [%0], [%1], 16;"
                 :: "r"(dst), "l"(src) : "memory");
}
__device__ __forceinline__ void cp_commit() {
    asm volatile("cp.async.commit_group;" ::: "memory");
}
template<int N>
__device__ __forceinline__ void cp_wait() {
    asm volatile("cp.async.wait_group %0;" :: "n"(N) : "memory");
}
__device__ __forceinline__ uint32_t split_pack_hi(float a, float b,
                                                  uint32_t& lo_pack) {
    __nv_bfloat16 h0 = __float2bfloat16(a);
    __nv_bfloat16 h1 = __float2bfloat16(b);
    __nv_bfloat16 l0 = __float2bfloat16(a - __bfloat162float(h0));
    __nv_bfloat16 l1 = __float2bfloat16(b - __bfloat162float(h1));
    lo_pack = (uint32_t)__bfloat16_as_ushort(l0)
            | ((uint32_t)__bfloat16_as_ushort(l1) << 16);
    return (uint32_t)__bfloat16_as_ushort(h0)
         | ((uint32_t)__bfloat16_as_ushort(h1) << 16);
}

// ---------------- scratch (device globals; no allocation allowed) ----------
__device__ float g_deg [NN];
__device__ float g_dinv[NN];
__device__ float g_aggx[(size_t)NN * 128];
__device__ float g_h2  [(size_t)NN * 64];
__device__ float g_z   [(size_t)NN * 64];
__device__ __nv_bfloat16 g_w1h[256 * 128],  g_w1l[256 * 128];   // [N][K]
__device__ __nv_bfloat16 g_w2h[64 * 256],   g_w2l[64 * 256];
__device__ __nv_bfloat16 g_wd1h[256 * 64],  g_wd1l[256 * 64];
__device__ __nv_bfloat16 g_wd2h[128 * 256], g_wd2l[128 * 256];

// ---------------- prep: all 4 weight splits (transposed) + deg init --------
__device__ __forceinline__ void splitw(const float* W, __nv_bfloat16* th,
                                       __nv_bfloat16* tl, int i, int K, int N) {
    int k = i / N, n = i % N;
    float v = W[i];
    __nv_bfloat16 h = __float2bfloat16(v);
    th[n * K + k] = h;
    tl[n * K + k] = __float2bfloat16(v - __bfloat162float(h));
}
__global__ void k_prep(const float* __restrict__ W1, const float* __restrict__ W2,
                       const float* __restrict__ Wd1, const float* __restrict__ Wd2)
{
    int i = blockIdx.x * 256 + threadIdx.x;
    if (i < 32768) {
        splitw(W1, g_w1h, g_w1l, i, 128, 256);
    } else if (i < 49152) {
        splitw(W2, g_w2h, g_w2l, i - 32768, 256, 64);
    } else if (i < 65536) {
        splitw(Wd1, g_wd1h, g_wd1l, i - 49152, 64, 256);
    } else if (i < 98304) {
        splitw(Wd2, g_wd2h, g_wd2l, i - 65536, 256, 128);
    } else {
        int n = i - 98304;
        if (n < NN) g_deg[n] = 1.0f;     // self-loop contributes 1
    }
}
__global__ void k_deg_count(const int* __restrict__ dst) {
    int e = blockIdx.x * 256 + threadIdx.x;
    if (e < ECNT) atomicAdd(&g_deg[dst[e]], 1.0f);
}

// -------- init aggregation: agg[i] = h[i]/deg[i]; stores dinv --------------
template<int C>
__global__ void k_init_agg(const float* __restrict__ h, float* __restrict__ agg)
{
    const int V = C / 4;
    int idx = blockIdx.x * 256 + threadIdx.x;
    if (idx >= NN * V) return;
    int node = idx / V;
    int v    = idx % V;
    float di = rsqrtf(g_deg[node]);
    if (v == 0) g_dinv[node] = di;
    float s = di * di;
    float4 hv = ((const float4*)h)[(size_t)node * V + v];
    float4 o;
    o.x = hv.x * s; o.y = hv.y * s; o.z = hv.z * s; o.w = hv.w * s;
    ((float4*)agg)[(size_t)node * V + v] = o;
}

// ---------------- edge scatter: agg[dst] += h[src] * dinv[src]*dinv[dst] ---
template<int C, int LPE>
__global__ void k_scatter(const int* __restrict__ src, const int* __restrict__ dst,
                          const float* __restrict__ h, float* __restrict__ agg)
{
    const int V = C / 4;
    int t   = blockIdx.x * 256 + threadIdx.x;
    int e   = t / LPE;
    int sub = t % LPE;
    if (e >= ECNT) return;
    int s = src[e];
    int d = dst[e];
    float norm = g_dinv[s] * g_dinv[d];
    const float4* hp = (const float4*)h   + (size_t)s * V;
    float4*       ap = (float4*)agg       + (size_t)d * V;
#pragma unroll
    for (int v = sub; v < V; v += LPE) {
        float4 hv = hp[v];
        float mx = hv.x * norm, my = hv.y * norm, mz = hv.z * norm, mw = hv.w * norm;
        asm volatile("red.global.add.v4.f32 [%0], {%1, %2, %3, %4};"
                     :: "l"(ap + v), "f"(mx), "f"(my), "f"(mz), "f"(mw)
                     : "memory");
    }
}

// ====== fused chain: Out = (relu(A@Wa + ba)) @ Wb  (+bb or ZINIT) ==========
// A: [M x K1] fp32 (split to smem hi/lo once). Wa: [256 x K1] pre-split bf16.
// mid = relu(A@Wa + ba) [M x 256], staged per 64-col chunk in smem hi/lo,
// never written to global. Wb: [N2 x 256] pre-split bf16, chunked by K.
// ZOUT: Out=h2 fp32 AND g_z = h2*dinv^2 + bb.  !ZOUT: Out = acc + bb.
template<int K1, int N2, bool ZOUT>
__global__ void __launch_bounds__(256, 1)
k_fused(const float* __restrict__ A,
        const __nv_bfloat16* __restrict__ Wah, const __nv_bfloat16* __restrict__ Wal,
        const float* __restrict__ ba,
        const __nv_bfloat16* __restrict__ Wbh, const __nv_bfloat16* __restrict__ Wbl,
        const float* __restrict__ bb, float* __restrict__ Out)
{
    constexpr int M    = NN;
    constexpr int NCH1 = K1 / 64;
    constexpr int ST   = 72;
    constexpr int A1   = 128 * ST * 2;      // 18432 per (chunk, arr)
    constexpr int WA1  = 64 * ST * 2;       //  9216 per (chunk, arr)
    constexpr int WAOFF  = NCH1 * 2 * A1;
    constexpr int MIDOFF = WAOFF + NCH1 * 2 * WA1;
    constexpr int WBOFF  = MIDOFF + 2 * A1;
    constexpr int WB1    = N2 * ST * 2;
    constexpr int NWCOL  = N2 / 2;          // cols per warp (wn)
    constexpr int NBB    = NWCOL / 16;      // 16-row B blocks per warp
    constexpr int NT2    = NWCOL / 8;       // 8-col tiles per warp

    extern __shared__ char smem[];
    uint32_t sb = smem_to_u32(smem);
    int tid = threadIdx.x, l = tid & 31, wid = tid >> 5;
    int wm = wid >> 1, wn = wid & 1;
    int bm = blockIdx.y * 128;

    // ---- load + split A (full K1) once ----
    for (int idx = tid; idx < 128 * (K1 / 2); idx += 256) {
        int row = idx / (K1 / 2);
        int col = (idx % (K1 / 2)) * 2;
        float2 v = make_float2(0.f, 0.f);
        int gr = bm + row;
        if (gr < M) v = *(const float2*)&A[(size_t)gr * K1 + col];
        uint32_t lp;
        uint32_t hp = split_pack_hi(v.x, v.y, lp);
        int c = col >> 6, cc = col & 63;
        uint32_t off = (uint32_t)(c * 2 * A1 + row * (ST * 2) + cc * 2);
        *(uint32_t*)(smem + off)      = hp;
        *(uint32_t*)(smem + off + A1) = lp;
    }

    int r8 = (l & 7) + ((l >> 3) & 1) * 8;
    int c8 = (l >> 4) * 8;
    uint32_t relA[2], relWa[2], relWb[NBB];
#pragma unroll
    for (int mt = 0; mt < 2; mt++)
        relA[mt] = (uint32_t)(((wm * 32 + mt * 16 + r8) * ST + c8) * 2);
#pragma unroll
    for (int nb = 0; nb < 2; nb++)
        relWa[nb] = (uint32_t)(((wn * 32 + nb * 16 + r8) * ST + c8) * 2);
#pragma unroll
    for (int nb = 0; nb < NBB; nb++)
        relWb[nb] = (uint32_t)(((wn * NWCOL + nb * 16 + r8) * ST + c8) * 2);

    float oacc[2][NT2][4];
#pragma unroll
    for (int mt = 0; mt < 2; mt++)
#pragma unroll
        for (int nt = 0; nt < NT2; nt++)
#pragma unroll
            for (int j = 0; j < 4; j++) oacc[mt][nt][j] = 0.0f;

    int g = l >> 2, tg = l & 3;

    for (int nc = 0; nc < 4; nc++) {
        // ---- load Wa chunk (rows nc*64..+64 of [256 x K1]) ----
        {
            constexpr int UA = NCH1 * 2 * 512;
            for (int i = tid; i < UA; i += 256) {
                int c   = i >> 10;
                int rem = i & 1023;
                int arr = rem >> 9;
                int r2  = rem & 511;
                int n   = r2 >> 3;
                int kc  = r2 & 7;
                const __nv_bfloat16* src =
                    (arr ? Wal : Wah) + (size_t)(nc * 64 + n) * K1 + c * 64 + kc * 8;
                cp16(sb + WAOFF + (uint32_t)((c * 2 + arr) * WA1
                                             + n * (ST * 2) + kc * 16), src);
            }
            // ---- load Wb chunk (cols nc*64..+64 of [N2 x 256]) ----
            constexpr int UB = N2 * 16;
            for (int i = tid; i < UB; i += 256) {
                int arr = i / (N2 * 8);
                int rem = i % (N2 * 8);
                int n   = rem >> 3;
                int kc  = rem & 7;
                const __nv_bfloat16* src =
                    (arr ? Wbl : Wbh) + (size_t)n * 256 + nc * 64 + kc * 8;
                cp16(sb + WBOFF + (uint32_t)(arr * WB1 + n * (ST * 2) + kc * 16), src);
            }
            cp_commit();
        }
        cp_wait<0>();
        __syncthreads();

        // ---- GEMM-a: macc = A @ Wa_chunk (128x64), 3-pass ----
        float macc[2][4][4];
#pragma unroll
        for (int mt = 0; mt < 2; mt++)
#pragma unroll
            for (int nt = 0; nt < 4; nt++)
#pragma unroll
                for (int j = 0; j < 4; j++) macc[mt][nt][j] = 0.0f;

#pragma unroll
        for (int c = 0; c < NCH1; c++) {
            uint32_t aBase = sb + (uint32_t)(c * 2 * A1);
            uint32_t wBase = sb + (uint32_t)(WAOFF + c * 2 * WA1);
#pragma unroll
            for (int ks = 0; ks < 4; ks++) {
                uint32_t ko = ks * 32;
                uint32_t ah0[4], ah1[4], al0[4], al1[4];
                uint32_t wh0[4], wh1[4], wl0[4], wl1[4];
                ldsm_x4(ah0, aBase + relA[0] + ko);
                ldsm_x4(ah1, aBase + relA[1] + ko);
                ldsm_x4(al0, aBase + A1 + relA[0] + ko);
                ldsm_x4(al1, aBase + A1 + relA[1] + ko);
                ldsm_x4(wh0, wBase + relWa[0] + ko);
                ldsm_x4(wh1, wBase + relWa[1] + ko);
                ldsm_x4(wl0, wBase + WA1 + relWa[0] + ko);
                ldsm_x4(wl1, wBase + WA1 + relWa[1] + ko);
#pragma unroll
                for (int mt = 0; mt < 2; mt++) {
                    const uint32_t* a_h = mt ? ah1 : ah0;
                    const uint32_t* a_l = mt ? al1 : al0;
#pragma unroll
                    for (int nt = 0; nt < 4; nt++) {
                        const uint32_t* b_h = (nt >> 1) ? wh1 : wh0;
                        const uint32_t* b_l = (nt >> 1) ? wl1 : wl0;
                        int sub = nt & 1;
                        mma_bf16(macc[mt][nt], a_h, b_h[sub], b_h[sub + 2]);
                        mma_bf16(macc[mt][nt], a_h, b_l[sub], b_l[sub + 2]);
                        mma_bf16(macc[mt][nt], a_l, b_h[sub], b_h[sub + 2]);
                    }
                }
            }
        }

        // ---- stage mid chunk: relu(macc + ba) -> smem hi/lo ----
#pragma unroll
        for (int mt = 0; mt < 2; mt++) {
            int row = wm * 32 + mt * 16 + g;
#pragma unroll
            for (int nt = 0; nt < 4; nt++) {
                int col = wn * 32 + nt * 8 + tg * 2;
                float2 bv = *(const float2*)&ba[nc * 64 + col];
                float2 o0 = make_float2(fmaxf(macc[mt][nt][0] + bv.x, 0.f),
                                        fmaxf(macc[mt][nt][1] + bv.y, 0.f));
                float2 o1 = make_float2(fmaxf(macc[mt][nt][2] + bv.x, 0.f),
                                        fmaxf(macc[mt][nt][3] + bv.y, 0.f));
                uint32_t lp, hp;
                hp = split_pack_hi(o0.x, o0.y, lp);
                *(uint32_t*)(smem + MIDOFF + (row * ST + col) * 2)      = hp;
                *(uint32_t*)(smem + MIDOFF + A1 + (row * ST + col) * 2) = lp;
                hp = split_pack_hi(o1.x, o1.y, lp);
                *(uint32_t*)(smem + MIDOFF + ((row + 8) * ST + col) * 2)      = hp;
                *(uint32_t*)(smem + MIDOFF + A1 + ((row + 8) * ST + col) * 2) = lp;
            }
        }
        __syncthreads();

        // ---- GEMM-b: oacc += mid_chunk @ Wb_chunk, 3-pass ----
#pragma unroll
        for (int ks = 0; ks < 4; ks++) {
            uint32_t ko = ks * 32;
            uint32_t mh0[4], mh1[4], ml0[4], ml1[4];
            ldsm_x4(mh0, sb + MIDOFF + relA[0] + ko);
            ldsm_x4(mh1, sb + MIDOFF + relA[1] + ko);
            ldsm_x4(ml0, sb + MIDOFF + A1 + relA[0] + ko);
            ldsm_x4(ml1, sb + MIDOFF + A1 + relA[1] + ko);
            uint32_t bh[NBB][4], bl[NBB][4];
#pragma unroll
            for (int nb = 0; nb < NBB; nb++) {
                ldsm_x4(bh[nb], sb + WBOFF + relWb[nb] + ko);
                ldsm_x4(bl[nb], sb + WBOFF + WB1 + relWb[nb] + ko);
            }
#pragma unroll
            for (int mt = 0; mt < 2; mt++) {
                const uint32_t* a_h = mt ? mh1 : mh0;
                const uint32_t* a_l = mt ? ml1 : ml0;
#pragma unroll
                for (int nt = 0; nt < NT2; nt++) {
                    int blk = nt >> 1, sub = nt & 1;
                    mma_bf16(oacc[mt][nt], a_h, bh[blk][sub], bh[blk][sub + 2]);
                    mma_bf16(oacc[mt][nt], a_h, bl[blk][sub], bl[blk][sub + 2]);
                    mma_bf16(oacc[mt][nt], a_l, bh[blk][sub], bh[blk][sub + 2]);
                }
            }
        }
        __syncthreads();   // buffers free for next chunk
    }

    // ---- final epilogue ----
#pragma unroll
    for (int mt = 0; mt < 2; mt++) {
        int row0 = bm + wm * 32 + mt * 16 + g;
        float zs0 = 0.f, zs1 = 0.f;
        if (ZOUT) {
            if (row0 < M)     { float d0 = g_dinv[row0];     zs0 = d0 * d0; }
            if (row0 + 8 < M) { float d1 = g_dinv[row0 + 8]; zs1 = d1 * d1; }
        }
#pragma unroll
        for (int nt = 0; nt < NT2; nt++) {
            int col = wn * NWCOL + nt * 8 + tg * 2;
            float2 o0 = make_float2(oacc[mt][nt][0], oacc[mt][nt][1]);
            float2 o1 = make_float2(oacc[mt][nt][2], oacc[mt][nt][3]);
            float2 bv = *(const float2*)&bb[col];
            if (!ZOUT) {
                o0.x += bv.x; o0.y += bv.y;
                o1.x += bv.x; o1.y += bv.y;
            }
            if (row0 < M) {
                *(float2*)&Out[(size_t)row0 * N2 + col] = o0;
                if (ZOUT) {
                    float2 zi = make_float2(fmaf(o0.x, zs0, bv.x),
                                            fmaf(o0.y, zs0, bv.y));
                    *(float2*)&g_z[(size_t)row0 * N2 + col] = zi;
                }
            }
            if (row0 + 8 < M) {
                *(float2*)&Out[(size_t)(row0 + 8) * N2 + col] = o1;
                if (ZOUT) {
                    float2 zi = make_float2(fmaf(o1.x, zs1, bv.x),
                                            fmaf(o1.y, zs1, bv.y));
                    *(float2*)&g_z[(size_t)(row0 + 8) * N2 + col] = zi;
                }
            }
        }
    }
}

// ---------------- launch ---------------------------------------------------
extern "C" void kernel_launch(void* const* d_in, const int* in_sizes, int n_in,
                              void* d_out, int out_size)
{
    const float* x   = (const float*)d_in[0];
    const int*   ei  = (const int*)  d_in[1];
    const float* W1  = (const float*)d_in[2];
    const float* b1  = (const float*)d_in[3];
    const float* W2  = (const float*)d_in[4];
    const float* b2  = (const float*)d_in[5];
    const float* Wd1 = (const float*)d_in[6];
    const float* bd1 = (const float*)d_in[7];
    const float* Wd2 = (const float*)d_in[8];
    const float* bd2 = (const float*)d_in[9];
    float* out = (float*)d_out;

    const int* srcp = ei;
    const int* dstp = ei + ECNT;

    float *p_aggx, *p_h2, *p_z;
    cudaGetSymbolAddress((void**)&p_aggx, g_aggx);
    cudaGetSymbolAddress((void**)&p_h2,   g_h2);
    cudaGetSymbolAddress((void**)&p_z,    g_z);
    __nv_bfloat16 *p_w1h, *p_w1l, *p_w2h, *p_w2l, *p_wd1h, *p_wd1l, *p_wd2h, *p_wd2l;
    cudaGetSymbolAddress((void**)&p_w1h, g_w1h);
    cudaGetSymbolAddress((void**)&p_w1l, g_w1l);
    cudaGetSymbolAddress((void**)&p_w2h, g_w2h);
    cudaGetSymbolAddress((void**)&p_w2l, g_w2l);
    cudaGetSymbolAddress((void**)&p_wd1h, g_wd1h);
    cudaGetSymbolAddress((void**)&p_wd1l, g_wd1l);
    cudaGetSymbolAddress((void**)&p_wd2h, g_wd2h);
    cudaGetSymbolAddress((void**)&p_wd2l, g_wd2l);

    // smem: L12 = 4*18432 + 4*9216 + 2*18432 + 2*9216  = 165888
    //       dec = 2*18432 + 2*9216 + 2*18432 + 2*18432 = 129024
    const int SM_L12 = 4 * 18432 + 4 * 9216 + 2 * 18432 + 2 * 9216;
    const int SM_DEC = 2 * 18432 + 2 * 9216 + 2 * 18432 + 2 * 18432;
    cudaFuncSetAttribute((const void*)k_fused<128, 64, true>,
                         cudaFuncAttributeMaxDynamicSharedMemorySize, SM_L12);
    cudaFuncSetAttribute((const void*)k_fused<64, 128, false>,
                         cudaFuncAttributeMaxDynamicSharedMemorySize, SM_DEC);

    // --- prep (weight splits + deg init) + degree count
    k_prep<<<(98304 + NN + 255) / 256, 256>>>(W1, W2, Wd1, Wd2);
    k_deg_count<<<(ECNT + 255) / 256, 256>>>(dstp);

    const int MB = (NN + 127) / 128;   // 391 row-blocks

    // --- layer 1+2: aggx = Dsym-scatter(x); fused h1->h2 (+z init)
    k_init_agg<128><<<(NN * 32 + 255) / 256, 256>>>(x, p_aggx);
    k_scatter<128,32><<<(ECNT * 32) / 256, 256>>>(srcp, dstp, x, p_aggx);
    k_fused<128, 64, true><<<dim3(1, MB), 256, SM_L12>>>(
        p_aggx, p_w1h, p_w1l, b1, p_w2h, p_w2l, b2, p_h2);

    // --- scatter layer 2 messages into z
    k_scatter<64,16><<<(ECNT * 16) / 256, 256>>>(srcp, dstp, p_h2, p_z);

    // --- decoder fused: out = relu(z@Wd1+bd1)@Wd2 + bd2
    k_fused<64, 128, false><<<dim3(1, MB), 256, SM_DEC>>>(
        p_z, p_wd1h, p_wd1l, bd1, p_wd2h, p_wd2l, bd2, out);
}

// round 13
// speedup vs baseline: 1.0414x; 1.0414x over previous
#include <cuda_runtime.h>
#include <cuda_bf16.h>
#include <cstdint>

#define NN   50000
#define ECNT 800000

// ===================== helpers =============================================
__device__ __forceinline__ uint32_t smem_to_u32(const void* p) {
    uint32_t a;
    asm("{ .reg .u64 t; cvta.to.shared.u64 t, %1; cvt.u32.u64 %0, t; }"
        : "=r"(a) : "l"(p));
    return a;
}
__device__ __forceinline__ void ldsm_x4(uint32_t* r, uint32_t addr) {
    asm volatile("ldmatrix.sync.aligned.m8n8.x4.shared.b16 {%0,%1,%2,%3}, [%4];"
        : "=r"(r[0]), "=r"(r[1]), "=r"(r[2]), "=r"(r[3]) : "r"(addr));
}
__device__ __forceinline__ void mma_bf16(float* c, const uint32_t* a,
                                         uint32_t b0, uint32_t b1) {
    asm volatile("mma.sync.aligned.m16n8k16.row.col.f32.bf16.bf16.f32 "
        "{%0,%1,%2,%3}, {%4,%5,%6,%7}, {%8,%9}, {%0,%1,%2,%3};"
        : "+f"(c[0]), "+f"(c[1]), "+f"(c[2]), "+f"(c[3])
        : "r"(a[0]), "r"(a[1]), "r"(a[2]), "r"(a[3]), "r"(b0), "r"(b1));
}
__device__ __forceinline__ void cp16(uint32_t dst, const void* src) {
    asm volatile("cp.async.cg.shared.global [%0], [%1], 16;"
                 :: "r"(dst), "l"(src) : "memory");
}
__device__ __forceinline__ void cp_commit() {
    asm volatile("cp.async.commit_group;" ::: "memory");
}
template<int N>
__device__ __forceinline__ void cp_wait() {
    asm volatile("cp.async.wait_group %0;" :: "n"(N) : "memory");
}
__device__ __forceinline__ uint32_t split_pack_hi(float a, float b,
                                                  uint32_t& lo_pack) {
    __nv_bfloat16 h0 = __float2bfloat16(a);
    __nv_bfloat16 h1 = __float2bfloat16(b);
    __nv_bfloat16 l0 = __float2bfloat16(a - __bfloat162float(h0));
    __nv_bfloat16 l1 = __float2bfloat16(b - __bfloat162float(h1));
    lo_pack = (uint32_t)__bfloat16_as_ushort(l0)
            | ((uint32_t)__bfloat16_as_ushort(l1) << 16);
    return (uint32_t)__bfloat16_as_ushort(h0)
         | ((uint32_t)__bfloat16_as_ushort(h1) << 16);
}

// ---------------- scratch (device globals; no allocation allowed) ----------
__device__ float g_deg [NN];
__device__ float g_dinv[NN];
__device__ float g_aggx[(size_t)NN * 128];
__device__ float g_h2  [(size_t)NN * 64];
__device__ float g_z   [(size_t)NN * 64];
__device__ __nv_bfloat16 g_axh[(size_t)NN * 128], g_axl[(size_t)NN * 128];
__device__ __nv_bfloat16 g_h1h[(size_t)NN * 256], g_h1l[(size_t)NN * 256];
__device__ __nv_bfloat16 g_zh [(size_t)NN * 64],  g_zl [(size_t)NN * 64];
__device__ __nv_bfloat16 g_dh [(size_t)NN * 256], g_dl [(size_t)NN * 256];
__device__ __nv_bfloat16 g_w1h[256 * 128],  g_w1l[256 * 128];   // [N][K]
__device__ __nv_bfloat16 g_w2h[64 * 256],   g_w2l[64 * 256];
__device__ __nv_bfloat16 g_wd1h[256 * 64],  g_wd1l[256 * 64];
__device__ __nv_bfloat16 g_wd2h[128 * 256], g_wd2l[128 * 256];

// ---------------- prep: all 4 weight splits (transposed) + deg init --------
__device__ __forceinline__ void splitw(const float* W, __nv_bfloat16* th,
                                       __nv_bfloat16* tl, int i, int K, int N) {
    int k = i / N, n = i % N;
    float v = W[i];
    __nv_bfloat16 h = __float2bfloat16(v);
    th[n * K + k] = h;
    tl[n * K + k] = __float2bfloat16(v - __bfloat162float(h));
}
__global__ void k_prep(const float* __restrict__ W1, const float* __restrict__ W2,
                       const float* __restrict__ Wd1, const float* __restrict__ Wd2)
{
    int i = blockIdx.x * 256 + threadIdx.x;
    if (i < 32768) {
        splitw(W1, g_w1h, g_w1l, i, 128, 256);
    } else if (i < 49152) {
        splitw(W2, g_w2h, g_w2l, i - 32768, 256, 64);
    } else if (i < 65536) {
        splitw(Wd1, g_wd1h, g_wd1l, i - 49152, 64, 256);
    } else if (i < 98304) {
        splitw(Wd2, g_wd2h, g_wd2l, i - 65536, 256, 128);
    } else {
        int n = i - 98304;
        if (n < NN) g_deg[n] = 1.0f;     // self-loop contributes 1
    }
}
__global__ void k_deg_count(const int* __restrict__ dst) {
    int e = blockIdx.x * 256 + threadIdx.x;
    if (e < ECNT) atomicAdd(&g_deg[dst[e]], 1.0f);
}

// ---------------- fp32 -> bf16 hi/lo split (flat, vectorized) --------------
__global__ void k_split(const float* __restrict__ in,
                        __nv_bfloat16* __restrict__ oh,
                        __nv_bfloat16* __restrict__ ol, int n4)
{
    int i = blockIdx.x * 256 + threadIdx.x;
    if (i >= n4) return;
    float4 v = ((const float4*)in)[i];
    uint32_t l0, l1;
    uint32_t h0 = split_pack_hi(v.x, v.y, l0);
    uint32_t h1 = split_pack_hi(v.z, v.w, l1);
    ((uint2*)oh)[i] = make_uint2(h0, h1);
    ((uint2*)ol)[i] = make_uint2(l0, l1);
}

// -------- init aggregation: agg[i] = h[i]/deg[i]; stores dinv --------------
template<int C>
__global__ void k_init_agg(const float* __restrict__ h, float* __restrict__ agg)
{
    const int V = C / 4;
    int idx = blockIdx.x * 256 + threadIdx.x;
    if (idx >= NN * V) return;
    int node = idx / V;
    int v    = idx % V;
    float di = rsqrtf(g_deg[node]);
    if (v == 0) g_dinv[node] = di;
    float s = di * di;
    float4 hv = ((const float4*)h)[(size_t)node * V + v];
    float4 o;
    o.x = hv.x * s; o.y = hv.y * s; o.z = hv.z * s; o.w = hv.w * s;
    ((float4*)agg)[(size_t)node * V + v] = o;
}

// ---------------- edge scatter: agg[dst] += h[src] * dinv[src]*dinv[dst] ---
template<int C, int LPE>
__global__ void k_scatter(const int* __restrict__ src, const int* __restrict__ dst,
                          const float* __restrict__ h, float* __restrict__ agg)
{
    const int V = C / 4;
    int t   = blockIdx.x * 256 + threadIdx.x;
    int e   = t / LPE;
    int sub = t % LPE;
    if (e >= ECNT) return;
    int s = src[e];
    int d = dst[e];
    float norm = g_dinv[s] * g_dinv[d];
    const float4* hp = (const float4*)h   + (size_t)s * V;
    float4*       ap = (float4*)agg       + (size_t)d * V;
#pragma unroll
    for (int v = sub; v < V; v += LPE) {
        float4 hv = hp[v];
        float mx = hv.x * norm, my = hv.y * norm, mz = hv.z * norm, mw = hv.w * norm;
        asm volatile("red.global.add.v4.f32 [%0], {%1, %2, %3, %4};"
                     :: "l"(ap + v), "f"(mx), "f"(my), "f"(mz), "f"(mw)
                     : "memory");
    }
}

// ============ bf16x3 tensor-core GEMM, TM=128, 2-stage cp.async ============
// (GEMM-1: bf16 split out; GEMM-3: bf16 split out)
template<int KTOT, int NTOT, bool BIAS, bool RELU>
__global__ void __launch_bounds__(256, 2)
k_gemm_bf(const __nv_bfloat16* __restrict__ Ah, const __nv_bfloat16* __restrict__ Al,
          const __nv_bfloat16* __restrict__ Bh, const __nv_bfloat16* __restrict__ Bl,
          const float* __restrict__ bias,
          __nv_bfloat16* __restrict__ Ch, __nv_bfloat16* __restrict__ Cl)
{
    constexpr int M  = NN;
    constexpr int TK = 64;
    constexpr int ST = 72;
    constexpr int NSTAGE = KTOT / TK;
    constexpr int A_SZ = 128 * ST * 2;
    constexpr int B_SZ = 64 * ST * 2;
    constexpr int STG  = 2 * A_SZ + 2 * B_SZ;

    extern __shared__ char smem[];
    uint32_t sb = smem_to_u32(smem);
    int tid = threadIdx.x, l = tid & 31, wid = tid >> 5;
    int wm = wid >> 1, wn = wid & 1;
    int bm = blockIdx.y * 128, bn = blockIdx.x * 64;

    float acc[2][4][4];
#pragma unroll
    for (int mt = 0; mt < 2; mt++)
#pragma unroll
        for (int nt = 0; nt < 4; nt++)
#pragma unroll
            for (int j = 0; j < 4; j++) acc[mt][nt][j] = 0.0f;

    int r8 = (l & 7) + ((l >> 3) & 1) * 8;
    int c8 = (l >> 4) * 8;
    uint32_t aAH[2], aAL[2], aBH[2], aBL[2];
#pragma unroll
    for (int mt = 0; mt < 2; mt++) {
        uint32_t o = (uint32_t)(((wm * 32 + mt * 16 + r8) * ST + c8) * 2);
        aAH[mt] = sb + o;
        aAL[mt] = sb + A_SZ + o;
    }
#pragma unroll
    for (int nb = 0; nb < 2; nb++) {
        uint32_t o = (uint32_t)(((wn * 32 + nb * 16 + r8) * ST + c8) * 2);
        aBH[nb] = sb + 2 * A_SZ + o;
        aBL[nb] = sb + 2 * A_SZ + B_SZ + o;
    }

    auto load_stage = [&](int s, int buf) {
        int k0 = s * TK;
        uint32_t base = sb + buf * STG;
#pragma unroll
        for (int it = 0; it < 8; it++) {
            int i   = tid + it * 256;
            int row = i >> 4;
            int sub = i & 15;
            int arr = sub >> 3;
            int ch  = sub & 7;
            int gr  = bm + row;
            if (gr < M) {
                const __nv_bfloat16* src =
                    (arr ? Al : Ah) + (size_t)gr * KTOT + k0 + ch * 8;
                cp16(base + arr * A_SZ + row * (ST * 2) + ch * 16, src);
            }
        }
#pragma unroll
        for (int it = 0; it < 4; it++) {
            int i   = tid + it * 256;
            int n   = i >> 4;
            int sub = i & 15;
            int arr = sub >> 3;
            int ch  = sub & 7;
            const __nv_bfloat16* src =
                (arr ? Bl : Bh) + (size_t)(bn + n) * KTOT + k0 + ch * 8;
            cp16(base + 2 * A_SZ + arr * B_SZ + n * (ST * 2) + ch * 16, src);
        }
        cp_commit();
    };

    load_stage(0, 0);

    for (int s = 0; s < NSTAGE; s++) {
        int buf = s & 1;
        if (s + 1 < NSTAGE) { load_stage(s + 1, buf ^ 1); cp_wait<1>(); }
        else                { cp_wait<0>(); }
        __syncthreads();

        uint32_t bo = buf * STG;
#pragma unroll
        for (int ks = 0; ks < TK / 16; ks++) {
            uint32_t koff = bo + ks * 32;
            uint32_t ah0[4], ah1[4], al0[4], al1[4];
            uint32_t bh0[4], bh1[4], bl0[4], bl1[4];
            ldsm_x4(ah0, aAH[0] + koff);
            ldsm_x4(ah1, aAH[1] + koff);
            ldsm_x4(al0, aAL[0] + koff);
            ldsm_x4(al1, aAL[1] + koff);
            ldsm_x4(bh0, aBH[0] + koff);
            ldsm_x4(bh1, aBH[1] + koff);
            ldsm_x4(bl0, aBL[0] + koff);
            ldsm_x4(bl1, aBL[1] + koff);
#pragma unroll
            for (int mt = 0; mt < 2; mt++) {
                const uint32_t* a_h = mt ? ah1 : ah0;
                const uint32_t* a_l = mt ? al1 : al0;
#pragma unroll
                for (int nt = 0; nt < 4; nt++) {
                    const uint32_t* b_h = (nt >> 1) ? bh1 : bh0;
                    const uint32_t* b_l = (nt >> 1) ? bl1 : bl0;
                    int sub = nt & 1;
                    mma_bf16(acc[mt][nt], a_h, b_h[sub], b_h[sub + 2]);
                    mma_bf16(acc[mt][nt], a_h, b_l[sub], b_l[sub + 2]);
                    mma_bf16(acc[mt][nt], a_l, b_h[sub], b_h[sub + 2]);
                }
            }
        }
        __syncthreads();
    }

    int g = l >> 2, tg = l & 3;
#pragma unroll
    for (int mt = 0; mt < 2; mt++) {
        int row0 = bm + wm * 32 + mt * 16 + g;
#pragma unroll
        for (int nt = 0; nt < 4; nt++) {
            int col = bn + wn * 32 + nt * 8 + tg * 2;
            float bx = 0.f, by = 0.f;
            if (BIAS) {
                float2 bv = *(const float2*)&bias[col];
                bx = bv.x; by = bv.y;
            }
            float2 o0 = make_float2(acc[mt][nt][0] + bx, acc[mt][nt][1] + by);
            float2 o1 = make_float2(acc[mt][nt][2] + bx, acc[mt][nt][3] + by);
            if (RELU) {
                o0.x = fmaxf(o0.x, 0.f); o0.y = fmaxf(o0.y, 0.f);
                o1.x = fmaxf(o1.x, 0.f); o1.y = fmaxf(o1.y, 0.f);
            }
            uint32_t lp;
            if (row0 < M) {
                uint32_t hp = split_pack_hi(o0.x, o0.y, lp);
                *(uint32_t*)&Ch[(size_t)row0 * NTOT + col] = hp;
                *(uint32_t*)&Cl[(size_t)row0 * NTOT + col] = lp;
            }
            if (row0 + 8 < M) {
                uint32_t hp = split_pack_hi(o1.x, o1.y, lp);
                *(uint32_t*)&Ch[(size_t)(row0 + 8) * NTOT + col] = hp;
                *(uint32_t*)&Cl[(size_t)(row0 + 8) * NTOT + col] = lp;
            }
        }
    }
}

// ============ TM=64 small-tile GEMM, 128 threads, fp32 out =================
// (GEMM-2 with ZINIT; GEMM-4 with BIAS) — better wave packing, occ 3.
template<int KTOT, int NTOT, bool BIAS, bool ZINIT>
__global__ void __launch_bounds__(128, 3)
k_gemm_sm(const __nv_bfloat16* __restrict__ Ah, const __nv_bfloat16* __restrict__ Al,
          const __nv_bfloat16* __restrict__ Bh, const __nv_bfloat16* __restrict__ Bl,
          const float* __restrict__ bias, float* __restrict__ Cf)
{
    constexpr int M  = NN;
    constexpr int TK = 64;
    constexpr int ST = 72;
    constexpr int NSTAGE = KTOT / TK;
    constexpr int A_SZ = 64 * ST * 2;     // 9216
    constexpr int B_SZ = 64 * ST * 2;     // 9216
    constexpr int STG  = 2 * A_SZ + 2 * B_SZ;  // 36864

    extern __shared__ char smem[];
    uint32_t sb = smem_to_u32(smem);
    int tid = threadIdx.x, l = tid & 31, wid = tid >> 5;
    int wm = wid >> 1, wn = wid & 1;          // 2m x 2n warps
    int bm = blockIdx.y * 64, bn = blockIdx.x * 64;

    float acc[2][4][4];
#pragma unroll
    for (int mt = 0; mt < 2; mt++)
#pragma unroll
        for (int nt = 0; nt < 4; nt++)
#pragma unroll
            for (int j = 0; j < 4; j++) acc[mt][nt][j] = 0.0f;

    int r8 = (l & 7) + ((l >> 3) & 1) * 8;
    int c8 = (l >> 4) * 8;
    uint32_t aAH[2], aAL[2], aBH[2], aBL[2];
#pragma unroll
    for (int mt = 0; mt < 2; mt++) {
        uint32_t o = (uint32_t)(((wm * 32 + mt * 16 + r8) * ST + c8) * 2);
        aAH[mt] = sb + o;
        aAL[mt] = sb + A_SZ + o;
    }
#pragma unroll
    for (int nb = 0; nb < 2; nb++) {
        uint32_t o = (uint32_t)(((wn * 32 + nb * 16 + r8) * ST + c8) * 2);
        aBH[nb] = sb + 2 * A_SZ + o;
        aBL[nb] = sb + 2 * A_SZ + B_SZ + o;
    }

    auto load_stage = [&](int s, int buf) {
        int k0 = s * TK;
        uint32_t base = sb + buf * STG;
#pragma unroll
        for (int it = 0; it < 8; it++) {      // A: 64 rows x 16 sub = 1024
            int i   = tid + it * 128;
            int row = i >> 4;
            int sub = i & 15;
            int arr = sub >> 3;
            int ch  = sub & 7;
            int gr  = bm + row;
            if (gr < M) {
                const __nv_bfloat16* src =
                    (arr ? Al : Ah) + (size_t)gr * KTOT + k0 + ch * 8;
                cp16(base + arr * A_SZ + row * (ST * 2) + ch * 16, src);
            }
        }
#pragma unroll
        for (int it = 0; it < 8; it++) {      // B: 64 rows x 16 sub = 1024
            int i   = tid + it * 128;
            int n   = i >> 4;
            int sub = i & 15;
            int arr = sub >> 3;
            int ch  = sub & 7;
            const __nv_bfloat16* src =
                (arr ? Bl : Bh) + (size_t)(bn + n) * KTOT + k0 + ch * 8;
            cp16(base + 2 * A_SZ + arr * B_SZ + n * (ST * 2) + ch * 16, src);
        }
        cp_commit();
    };

    load_stage(0, 0);

    for (int s = 0; s < NSTAGE; s++) {
        int buf = s & 1;
        if (s + 1 < NSTAGE) { load_stage(s + 1, buf ^ 1); cp_wait<1>(); }
        else                { cp_wait<0>(); }
        __syncthreads();

        uint32_t bo = buf * STG;
#pragma unroll
        for (int ks = 0; ks < TK / 16; ks++) {
            uint32_t koff = bo + ks * 32;
            uint32_t ah0[4], ah1[4], al0[4], al1[4];
            uint32_t bh0[4], bh1[4], bl0[4], bl1[4];
            ldsm_x4(ah0, aAH[0] + koff);
            ldsm_x4(ah1, aAH[1] + koff);
            ldsm_x4(al0, aAL[0] + koff);
            ldsm_x4(al1, aAL[1] + koff);
            ldsm_x4(bh0, aBH[0] + koff);
            ldsm_x4(bh1, aBH[1] + koff);
            ldsm_x4(bl0, aBL[0] + koff);
            ldsm_x4(bl1, aBL[1] + koff);
#pragma unroll
            for (int mt = 0; mt < 2; mt++) {
                const uint32_t* a_h = mt ? ah1 : ah0;
                const uint32_t* a_l = mt ? al1 : al0;
#pragma unroll
                for (int nt = 0; nt < 4; nt++) {
                    const uint32_t* b_h = (nt >> 1) ? bh1 : bh0;
                    const uint32_t* b_l = (nt >> 1) ? bl1 : bl0;
                    int sub = nt & 1;
                    mma_bf16(acc[mt][nt], a_h, b_h[sub], b_h[sub + 2]);
                    mma_bf16(acc[mt][nt], a_h, b_l[sub], b_l[sub + 2]);
                    mma_bf16(acc[mt][nt], a_l, b_h[sub], b_h[sub + 2]);
                }
            }
        }
        __syncthreads();
    }

    int g = l >> 2, tg = l & 3;
#pragma unroll
    for (int mt = 0; mt < 2; mt++) {
        int row0 = bm + wm * 32 + mt * 16 + g;
        float zs0 = 0.f, zs1 = 0.f;
        if (ZINIT) {
            if (row0 < M)     { float d0 = g_dinv[row0];     zs0 = d0 * d0; }
            if (row0 + 8 < M) { float d1 = g_dinv[row0 + 8]; zs1 = d1 * d1; }
        }
#pragma unroll
        for (int nt = 0; nt < 4; nt++) {
            int col = bn + wn * 32 + nt * 8 + tg * 2;
            float bx = 0.f, by = 0.f;
            if (BIAS) {
                float2 bv = *(const float2*)&bias[col];
                bx = bv.x; by = bv.y;
            }
            float2 o0 = make_float2(acc[mt][nt][0] + bx, acc[mt][nt][1] + by);
            float2 o1 = make_float2(acc[mt][nt][2] + bx, acc[mt][nt][3] + by);
            if (row0 < M) {
                *(float2*)&Cf[(size_t)row0 * NTOT + col] = o0;
                if (ZINIT) {
                    float2 bz = *(const float2*)&bias[col];
                    float2 zi = make_float2(fmaf(o0.x, zs0, bz.x),
                                            fmaf(o0.y, zs0, bz.y));
                    *(float2*)&g_z[(size_t)row0 * NTOT + col] = zi;
                }
            }
            if (row0 + 8 < M) {
                *(float2*)&Cf[(size_t)(row0 + 8) * NTOT + col] = o1;
                if (ZINIT) {
                    float2 bz = *(const float2*)&bias[col];
                    float2 zi = make_float2(fmaf(o1.x, zs1, bz.x),
                                            fmaf(o1.y, zs1, bz.y));
                    *(float2*)&g_z[(size_t)(row0 + 8) * NTOT + col] = zi;
                }
            }
        }
    }
}

// ---------------- launch ---------------------------------------------------
extern "C" void kernel_launch(void* const* d_in, const int* in_sizes, int n_in,
                              void* d_out, int out_size)
{
    const float* x   = (const float*)d_in[0];
    const int*   ei  = (const int*)  d_in[1];
    const float* W1  = (const float*)d_in[2];
    const float* b1  = (const float*)d_in[3];
    const float* W2  = (const float*)d_in[4];
    const float* b2  = (const float*)d_in[5];
    const float* Wd1 = (const float*)d_in[6];
    const float* bd1 = (const float*)d_in[7];
    const float* Wd2 = (const float*)d_in[8];
    const float* bd2 = (const float*)d_in[9];
    float* out = (float*)d_out;

    const int* srcp = ei;
    const int* dstp = ei + ECNT;

    float *p_aggx, *p_h2, *p_z;
    cudaGetSymbolAddress((void**)&p_aggx, g_aggx);
    cudaGetSymbolAddress((void**)&p_h2,   g_h2);
    cudaGetSymbolAddress((void**)&p_z,    g_z);
    __nv_bfloat16 *p_axh, *p_axl, *p_h1h, *p_h1l, *p_zh, *p_zl, *p_dh, *p_dl;
    __nv_bfloat16 *p_w1h, *p_w1l, *p_w2h, *p_w2l, *p_wd1h, *p_wd1l, *p_wd2h, *p_wd2l;
    cudaGetSymbolAddress((void**)&p_axh, g_axh);
    cudaGetSymbolAddress((void**)&p_axl, g_axl);
    cudaGetSymbolAddress((void**)&p_h1h, g_h1h);
    cudaGetSymbolAddress((void**)&p_h1l, g_h1l);
    cudaGetSymbolAddress((void**)&p_zh,  g_zh);
    cudaGetSymbolAddress((void**)&p_zl,  g_zl);
    cudaGetSymbolAddress((void**)&p_dh,  g_dh);
    cudaGetSymbolAddress((void**)&p_dl,  g_dl);
    cudaGetSymbolAddress((void**)&p_w1h, g_w1h);
    cudaGetSymbolAddress((void**)&p_w1l, g_w1l);
    cudaGetSymbolAddress((void**)&p_w2h, g_w2h);
    cudaGetSymbolAddress((void**)&p_w2l, g_w2l);
    cudaGetSymbolAddress((void**)&p_wd1h, g_wd1h);
    cudaGetSymbolAddress((void**)&p_wd1l, g_wd1l);
    cudaGetSymbolAddress((void**)&p_wd2h, g_wd2h);
    cudaGetSymbolAddress((void**)&p_wd2l, g_wd2l);

    const int STG  = 2 * (128 * 72 * 2) + 2 * (64 * 72 * 2);  // 55296
    const int STGS = 2 * (2 * (64 * 72 * 2) + 2 * (64 * 72 * 2));  // 73728
    cudaFuncSetAttribute((const void*)k_gemm_bf<128, 256, true, true>,
                         cudaFuncAttributeMaxDynamicSharedMemorySize, 2 * STG);
    cudaFuncSetAttribute((const void*)k_gemm_bf<64,  256, true, true>,
                         cudaFuncAttributeMaxDynamicSharedMemorySize, STG);
    cudaFuncSetAttribute((const void*)k_gemm_sm<256, 64,  false, true >,
                         cudaFuncAttributeMaxDynamicSharedMemorySize, STGS);
    cudaFuncSetAttribute((const void*)k_gemm_sm<256, 128, true,  false>,
                         cudaFuncAttributeMaxDynamicSharedMemorySize, STGS);

    // --- prep (weight splits + deg init) + degree count
    k_prep<<<(98304 + NN + 255) / 256, 256>>>(W1, W2, Wd1, Wd2);
    k_deg_count<<<(ECNT + 255) / 256, 256>>>(dstp);

    const int MB   = (NN + 127) / 128;   // 391
    const int MB64 = (NN + 63)  / 64;    // 782

    // --- layer 1: aggx = Dsym-scatter(x); split; h1 = relu(aggx@W1+b1)
    k_init_agg<128><<<(NN * 32 + 255) / 256, 256>>>(x, p_aggx);
    k_scatter<128,32><<<(ECNT * 32) / 256, 256>>>(srcp, dstp, x, p_aggx);
    k_split<<<(NN * 32 + 255) / 256, 256>>>(p_aggx, p_axh, p_axl, NN * 32);
    k_gemm_bf<128, 256, true, true><<<dim3(4, MB), 256, 2 * STG>>>(
        p_axh, p_axl, p_w1h, p_w1l, b1, p_h1h, p_h1l);

    // --- layer 2: h2 = h1 @ W2 [small tiles, fused z-init]; scatter; split
    k_gemm_sm<256, 64, false, true><<<dim3(1, MB64), 128, STGS>>>(
        p_h1h, p_h1l, p_w2h, p_w2l, b2, p_h2);
    k_scatter<64,16><<<(ECNT * 16) / 256, 256>>>(srcp, dstp, p_h2, p_z);
    k_split<<<(NN * 16 + 255) / 256, 256>>>(p_z, p_zh, p_zl, NN * 16);

    // --- decoder: d = relu(z @ Wd1 + bd1); out = d @ Wd2 + bd2 [small tiles]
    k_gemm_bf<64, 256, true, true><<<dim3(4, MB), 256, STG>>>(
        p_zh, p_zl, p_wd1h, p_wd1l, bd1, p_dh, p_dl);
    k_gemm_sm<256, 128, true, false><<<dim3(2, MB64), 128, STGS>>>(
        p_dh, p_dl, p_wd2h, p_wd2l, bd2, out);
}

// round 14
// speedup vs baseline: 1.1298x; 1.0849x over previous
#include <cuda_runtime.h>
#include <cuda_bf16.h>
#include <cstdint>

#define NN   50000
#define ECNT 800000

// ===================== helpers =============================================
__device__ __forceinline__ uint32_t smem_to_u32(const void* p) {
    uint32_t a;
    asm("{ .reg .u64 t; cvta.to.shared.u64 t, %1; cvt.u32.u64 %0, t; }"
        : "=r"(a) : "l"(p));
    return a;
}
__device__ __forceinline__ void ldsm_x4(uint32_t* r, uint32_t addr) {
    asm volatile("ldmatrix.sync.aligned.m8n8.x4.shared.b16 {%0,%1,%2,%3}, [%4];"
        : "=r"(r[0]), "=r"(r[1]), "=r"(r[2]), "=r"(r[3]) : "r"(addr));
}
__device__ __forceinline__ void mma_bf16(float* c, const uint32_t* a,
                                         uint32_t b0, uint32_t b1) {
    asm volatile("mma.sync.aligned.m16n8k16.row.col.f32.bf16.bf16.f32 "
        "{%0,%1,%2,%3}, {%4,%5,%6,%7}, {%8,%9}, {%0,%1,%2,%3};"
        : "+f"(c[0]), "+f"(c[1]), "+f"(c[2]), "+f"(c[3])
        : "r"(a[0]), "r"(a[1]), "r"(a[2]), "r"(a[3]), "r"(b0), "r"(b1));
}
__device__ __forceinline__ void cp16(uint32_t dst, const void* src) {
    asm volatile("cp.async.cg.shared.global [%0], [%1], 16;"
                 :: "r"(dst), "l"(src) : "memory");
}
__device__ __forceinline__ void cp_commit() {
    asm volatile("cp.async.commit_group;" ::: "memory");
}
template<int N>
__device__ __forceinline__ void cp_wait() {
    asm volatile("cp.async.wait_group %0;" :: "n"(N) : "memory");
}
__device__ __forceinline__ void red4(float* addr, float a, float b, float c, float d) {
    asm volatile("red.global.add.v4.f32 [%0], {%1, %2, %3, %4};"
                 :: "l"(addr), "f"(a), "f"(b), "f"(c), "f"(d) : "memory");
}
__device__ __forceinline__ uint32_t split_pack_hi(float a, float b,
                                                  uint32_t& lo_pack) {
    __nv_bfloat16 h0 = __float2bfloat16(a);
    __nv_bfloat16 h1 = __float2bfloat16(b);
    __nv_bfloat16 l0 = __float2bfloat16(a - __bfloat162float(h0));
    __nv_bfloat16 l1 = __float2bfloat16(b - __bfloat162float(h1));
    lo_pack = (uint32_t)__bfloat16_as_ushort(l0)
            | ((uint32_t)__bfloat16_as_ushort(l1) << 16);
    return (uint32_t)__bfloat16_as_ushort(h0)
         | ((uint32_t)__bfloat16_as_ushort(h1) << 16);
}

// ---------------- scratch (device globals; no allocation allowed) ----------
__device__ float g_deg [NN];
__device__ float g_dinv[NN];
__device__ float g_aggx[(size_t)NN * 128];
__device__ float g_h2  [(size_t)NN * 64];
__device__ float g_z   [(size_t)NN * 64];
__device__ __nv_bfloat16 g_axh[(size_t)NN * 128], g_axl[(size_t)NN * 128];
__device__ __nv_bfloat16 g_h1h[(size_t)NN * 256], g_h1l[(size_t)NN * 256];
__device__ __nv_bfloat16 g_zh [(size_t)NN * 64],  g_zl [(size_t)NN * 64];
__device__ __nv_bfloat16 g_dh [(size_t)NN * 256], g_dl [(size_t)NN * 256];
__device__ __nv_bfloat16 g_w1h[256 * 128],  g_w1l[256 * 128];   // [N][K]
__device__ __nv_bfloat16 g_w2h[64 * 256],   g_w2l[64 * 256];
__device__ __nv_bfloat16 g_wd1h[256 * 64],  g_wd1l[256 * 64];
__device__ __nv_bfloat16 g_wd2h[128 * 256], g_wd2l[128 * 256];

// ---------------- prep: all 4 weight splits (transposed) + deg init --------
__device__ __forceinline__ void splitw(const float* W, __nv_bfloat16* th,
                                       __nv_bfloat16* tl, int i, int K, int N) {
    int k = i / N, n = i % N;
    float v = W[i];
    __nv_bfloat16 h = __float2bfloat16(v);
    th[n * K + k] = h;
    tl[n * K + k] = __float2bfloat16(v - __bfloat162float(h));
}
__global__ void k_prep(const float* __restrict__ W1, const float* __restrict__ W2,
                       const float* __restrict__ Wd1, const float* __restrict__ Wd2)
{
    int i = blockIdx.x * 256 + threadIdx.x;
    if (i < 32768) {
        splitw(W1, g_w1h, g_w1l, i, 128, 256);
    } else if (i < 49152) {
        splitw(W2, g_w2h, g_w2l, i - 32768, 256, 64);
    } else if (i < 65536) {
        splitw(Wd1, g_wd1h, g_wd1l, i - 49152, 64, 256);
    } else if (i < 98304) {
        splitw(Wd2, g_wd2h, g_wd2l, i - 65536, 256, 128);
    } else {
        int n = i - 98304;
        if (n < NN) g_deg[n] = 1.0f;     // self-loop contributes 1
    }
}
__global__ void k_deg_count(const int* __restrict__ dst) {
    int e = blockIdx.x * 256 + threadIdx.x;
    if (e < ECNT) atomicAdd(&g_deg[dst[e]], 1.0f);
}

// ---------------- fp32 -> bf16 hi/lo split (flat, vectorized) --------------
__global__ void k_split(const float* __restrict__ in,
                        __nv_bfloat16* __restrict__ oh,
                        __nv_bfloat16* __restrict__ ol, int n4)
{
    int i = blockIdx.x * 256 + threadIdx.x;
    if (i >= n4) return;
    float4 v = ((const float4*)in)[i];
    uint32_t l0, l1;
    uint32_t h0 = split_pack_hi(v.x, v.y, l0);
    uint32_t h1 = split_pack_hi(v.z, v.w, l1);
    ((uint2*)oh)[i] = make_uint2(h0, h1);
    ((uint2*)ol)[i] = make_uint2(l0, l1);
}

// -------- init aggregation: agg[i] = h[i]/deg[i]; stores dinv --------------
template<int C>
__global__ void k_init_agg(const float* __restrict__ h, float* __restrict__ agg)
{
    const int V = C / 4;
    int idx = blockIdx.x * 256 + threadIdx.x;
    if (idx >= NN * V) return;
    int node = idx / V;
    int v    = idx % V;
    float di = rsqrtf(g_deg[node]);
    if (v == 0) g_dinv[node] = di;
    float s = di * di;
    float4 hv = ((const float4*)h)[(size_t)node * V + v];
    float4 o;
    o.x = hv.x * s; o.y = hv.y * s; o.z = hv.z * s; o.w = hv.w * s;
    ((float4*)agg)[(size_t)node * V + v] = o;
}

// ===== edge scatter, 4 edges/warp batched (128 ch; lane = channel quad) ====
__global__ void __launch_bounds__(256)
k_scat1(const int* __restrict__ src, const int* __restrict__ dst,
        const float* __restrict__ x, float* __restrict__ agg)
{
    const int EPW = 4;
    int warp = (blockIdx.x * 256 + threadIdx.x) >> 5;   // 0..199999
    int lane = threadIdx.x & 31;
    int e0 = warp * EPW;                                 // exact: 800000/4
    int s[EPW], d[EPW];
    float nr[EPW];
#pragma unroll
    for (int k = 0; k < EPW; k++) {
        s[k] = __ldg(&src[e0 + k]);
        d[k] = __ldg(&dst[e0 + k]);
    }
    float ds[EPW], dd[EPW];
#pragma unroll
    for (int k = 0; k < EPW; k++) ds[k] = __ldg(&g_dinv[s[k]]);
#pragma unroll
    for (int k = 0; k < EPW; k++) dd[k] = __ldg(&g_dinv[d[k]]);
#pragma unroll
    for (int k = 0; k < EPW; k++) nr[k] = ds[k] * dd[k];
    float4 v[EPW];
#pragma unroll
    for (int k = 0; k < EPW; k++)
        v[k] = __ldg((const float4*)x + (size_t)s[k] * 32 + lane);
#pragma unroll
    for (int k = 0; k < EPW; k++)
        red4((float*)((float4*)agg + (size_t)d[k] * 32 + lane),
             v[k].x * nr[k], v[k].y * nr[k], v[k].z * nr[k], v[k].w * nr[k]);
}

// ===== edge scatter, 8 edges/warp (64 ch; 16 quads x 2 edge slots) =========
__global__ void __launch_bounds__(256)
k_scat2(const int* __restrict__ src, const int* __restrict__ dst,
        const float* __restrict__ h, float* __restrict__ agg)
{
    const int EPW = 8;
    int warp = (blockIdx.x * 256 + threadIdx.x) >> 5;   // 0..99999
    int lane = threadIdx.x & 31;
    int sub  = lane & 15;         // channel quad (64ch = 16 quads)
    int half = lane >> 4;         // edge slot
    int e0 = warp * EPW + half;                          // exact: 800000/8
    int s[4], d[4];
    float nr[4];
#pragma unroll
    for (int k = 0; k < 4; k++) {
        s[k] = __ldg(&src[e0 + 2 * k]);
        d[k] = __ldg(&dst[e0 + 2 * k]);
    }
    float ds[4], dd[4];
#pragma unroll
    for (int k = 0; k < 4; k++) ds[k] = __ldg(&g_dinv[s[k]]);
#pragma unroll
    for (int k = 0; k < 4; k++) dd[k] = __ldg(&g_dinv[d[k]]);
#pragma unroll
    for (int k = 0; k < 4; k++) nr[k] = ds[k] * dd[k];
    float4 v[4];
#pragma unroll
    for (int k = 0; k < 4; k++)
        v[k] = __ldg((const float4*)h + (size_t)s[k] * 16 + sub);
#pragma unroll
    for (int k = 0; k < 4; k++)
        red4((float*)((float4*)agg + (size_t)d[k] * 16 + sub),
             v[k].x * nr[k], v[k].y * nr[k], v[k].z * nr[k], v[k].w * nr[k]);
}

// ============ bf16x3 tensor-core GEMM, 2-stage cp.async pipeline ===========
// Output modes: fp32 (Cf) | hi/lo-split bf16 (Ch,Cl) | ZINIT: Cf=h2 AND
// g_z = h2*dinv^2 + bias (fused layer-2 aggregation init).
template<int KTOT, int NTOT, bool BIAS, bool RELU, bool SPLIT, bool ZINIT>
__global__ void __launch_bounds__(256, 2)
k_gemm_bf(const __nv_bfloat16* __restrict__ Ah, const __nv_bfloat16* __restrict__ Al,
          const __nv_bfloat16* __restrict__ Bh, const __nv_bfloat16* __restrict__ Bl,
          const float* __restrict__ bias, float* __restrict__ Cf,
          __nv_bfloat16* __restrict__ Ch, __nv_bfloat16* __restrict__ Cl)
{
    constexpr int M  = NN;
    constexpr int TK = 64;
    constexpr int ST = 72;
    constexpr int NSTAGE = KTOT / TK;
    constexpr int A_SZ = 128 * ST * 2;
    constexpr int B_SZ = 64 * ST * 2;
    constexpr int STG  = 2 * A_SZ + 2 * B_SZ;
    constexpr int PIPE = (NSTAGE > 1) ? 2 : 1;

    extern __shared__ char smem[];
    uint32_t sb = smem_to_u32(smem);
    int tid = threadIdx.x, l = tid & 31, wid = tid >> 5;
    int wm = wid >> 1, wn = wid & 1;
    int bm = blockIdx.y * 128, bn = blockIdx.x * 64;

    float acc[2][4][4];
#pragma unroll
    for (int mt = 0; mt < 2; mt++)
#pragma unroll
        for (int nt = 0; nt < 4; nt++)
#pragma unroll
            for (int j = 0; j < 4; j++) acc[mt][nt][j] = 0.0f;

    int r8 = (l & 7) + ((l >> 3) & 1) * 8;
    int c8 = (l >> 4) * 8;
    uint32_t aAH[2], aAL[2], aBH[2], aBL[2];
#pragma unroll
    for (int mt = 0; mt < 2; mt++) {
        uint32_t o = (uint32_t)(((wm * 32 + mt * 16 + r8) * ST + c8) * 2);
        aAH[mt] = sb + o;
        aAL[mt] = sb + A_SZ + o;
    }
#pragma unroll
    for (int nb = 0; nb < 2; nb++) {
        uint32_t o = (uint32_t)(((wn * 32 + nb * 16 + r8) * ST + c8) * 2);
        aBH[nb] = sb + 2 * A_SZ + o;
        aBL[nb] = sb + 2 * A_SZ + B_SZ + o;
    }

    auto load_stage = [&](int s, int buf) {
        int k0 = s * TK;
        uint32_t base = sb + buf * STG;
#pragma unroll
        for (int it = 0; it < 8; it++) {
            int i   = tid + it * 256;
            int row = i >> 4;
            int sub = i & 15;
            int arr = sub >> 3;
            int ch  = sub & 7;
            int gr  = bm + row;
            if (gr < M) {
                const __nv_bfloat16* src =
                    (arr ? Al : Ah) + (size_t)gr * KTOT + k0 + ch * 8;
                cp16(base + arr * A_SZ + row * (ST * 2) + ch * 16, src);
            }
        }
#pragma unroll
        for (int it = 0; it < 4; it++) {
            int i   = tid + it * 256;
            int n   = i >> 4;
            int sub = i & 15;
            int arr = sub >> 3;
            int ch  = sub & 7;
            const __nv_bfloat16* src =
                (arr ? Bl : Bh) + (size_t)(bn + n) * KTOT + k0 + ch * 8;
            cp16(base + 2 * A_SZ + arr * B_SZ + n * (ST * 2) + ch * 16, src);
        }
        cp_commit();
    };

    load_stage(0, 0);

    for (int s = 0; s < NSTAGE; s++) {
        int buf = (PIPE == 2) ? (s & 1) : 0;
        if (PIPE == 2 && s + 1 < NSTAGE) load_stage(s + 1, buf ^ 1);
        if (PIPE == 2 && s + 1 < NSTAGE) cp_wait<1>(); else cp_wait<0>();
        __syncthreads();

        uint32_t bo = buf * STG;
#pragma unroll
        for (int ks = 0; ks < TK / 16; ks++) {
            uint32_t koff = bo + ks * 32;
            uint32_t ah0[4], ah1[4], al0[4], al1[4];
            uint32_t bh0[4], bh1[4], bl0[4], bl1[4];
            ldsm_x4(ah0, aAH[0] + koff);
            ldsm_x4(ah1, aAH[1] + koff);
            ldsm_x4(al0, aAL[0] + koff);
            ldsm_x4(al1, aAL[1] + koff);
            ldsm_x4(bh0, aBH[0] + koff);
            ldsm_x4(bh1, aBH[1] + koff);
            ldsm_x4(bl0, aBL[0] + koff);
            ldsm_x4(bl1, aBL[1] + koff);
#pragma unroll
            for (int mt = 0; mt < 2; mt++) {
                const uint32_t* a_h = mt ? ah1 : ah0;
                const uint32_t* a_l = mt ? al1 : al0;
#pragma unroll
                for (int nt = 0; nt < 4; nt++) {
                    const uint32_t* b_h = (nt >> 1) ? bh1 : bh0;
                    const uint32_t* b_l = (nt >> 1) ? bl1 : bl0;
                    int sub = nt & 1;
                    mma_bf16(acc[mt][nt], a_h, b_h[sub], b_h[sub + 2]);
                    mma_bf16(acc[mt][nt], a_h, b_l[sub], b_l[sub + 2]);
                    mma_bf16(acc[mt][nt], a_l, b_h[sub], b_h[sub + 2]);
                }
            }
        }
        __syncthreads();
    }

    int g = l >> 2, tg = l & 3;
#pragma unroll
    for (int mt = 0; mt < 2; mt++) {
        int row0 = bm + wm * 32 + mt * 16 + g;
        float zs0 = 0.f, zs1 = 0.f;
        if (ZINIT) {
            if (row0 < M)     { float d0 = g_dinv[row0];     zs0 = d0 * d0; }
            if (row0 + 8 < M) { float d1 = g_dinv[row0 + 8]; zs1 = d1 * d1; }
        }
#pragma unroll
        for (int nt = 0; nt < 4; nt++) {
            int col = bn + wn * 32 + nt * 8 + tg * 2;
            float bx = 0.f, by = 0.f;
            if (BIAS) {
                float2 bv = *(const float2*)&bias[col];
                bx = bv.x; by = bv.y;
            }
            float2 o0 = make_float2(acc[mt][nt][0] + bx, acc[mt][nt][1] + by);
            float2 o1 = make_float2(acc[mt][nt][2] + bx, acc[mt][nt][3] + by);
            if (RELU) {
                o0.x = fmaxf(o0.x, 0.f); o0.y = fmaxf(o0.y, 0.f);
                o1.x = fmaxf(o1.x, 0.f); o1.y = fmaxf(o1.y, 0.f);
            }
            if (SPLIT) {
                uint32_t lp;
                if (row0 < M) {
                    uint32_t hp = split_pack_hi(o0.x, o0.y, lp);
                    *(uint32_t*)&Ch[(size_t)row0 * NTOT + col] = hp;
                    *(uint32_t*)&Cl[(size_t)row0 * NTOT + col] = lp;
                }
                if (row0 + 8 < M) {
                    uint32_t hp = split_pack_hi(o1.x, o1.y, lp);
                    *(uint32_t*)&Ch[(size_t)(row0 + 8) * NTOT + col] = hp;
                    *(uint32_t*)&Cl[(size_t)(row0 + 8) * NTOT + col] = lp;
                }
            } else {
                if (row0 < M) {
                    *(float2*)&Cf[(size_t)row0 * NTOT + col] = o0;
                    if (ZINIT) {
                        float2 bz = *(const float2*)&bias[col];
                        float2 zi = make_float2(fmaf(o0.x, zs0, bz.x),
                                                fmaf(o0.y, zs0, bz.y));
                        *(float2*)&g_z[(size_t)row0 * NTOT + col] = zi;
                    }
                }
                if (row0 + 8 < M) {
                    *(float2*)&Cf[(size_t)(row0 + 8) * NTOT + col] = o1;
                    if (ZINIT) {
                        float2 bz = *(const float2*)&bias[col];
                        float2 zi = make_float2(fmaf(o1.x, zs1, bz.x),
                                                fmaf(o1.y, zs1, bz.y));
                        *(float2*)&g_z[(size_t)(row0 + 8) * NTOT + col] = zi;
                    }
                }
            }
        }
    }
}

// ---------------- launch ---------------------------------------------------
extern "C" void kernel_launch(void* const* d_in, const int* in_sizes, int n_in,
                              void* d_out, int out_size)
{
    const float* x   = (const float*)d_in[0];
    const int*   ei  = (const int*)  d_in[1];
    const float* W1  = (const float*)d_in[2];
    const float* b1  = (const float*)d_in[3];
    const float* W2  = (const float*)d_in[4];
    const float* b2  = (const float*)d_in[5];
    const float* Wd1 = (const float*)d_in[6];
    const float* bd1 = (const float*)d_in[7];
    const float* Wd2 = (const float*)d_in[8];
    const float* bd2 = (const float*)d_in[9];
    float* out = (float*)d_out;

    const int* srcp = ei;
    const int* dstp = ei + ECNT;

    float *p_aggx, *p_h2, *p_z;
    cudaGetSymbolAddress((void**)&p_aggx, g_aggx);
    cudaGetSymbolAddress((void**)&p_h2,   g_h2);
    cudaGetSymbolAddress((void**)&p_z,    g_z);
    __nv_bfloat16 *p_axh, *p_axl, *p_h1h, *p_h1l, *p_zh, *p_zl, *p_dh, *p_dl;
    __nv_bfloat16 *p_w1h, *p_w1l, *p_w2h, *p_w2l, *p_wd1h, *p_wd1l, *p_wd2h, *p_wd2l;
    cudaGetSymbolAddress((void**)&p_axh, g_axh);
    cudaGetSymbolAddress((void**)&p_axl, g_axl);
    cudaGetSymbolAddress((void**)&p_h1h, g_h1h);
    cudaGetSymbolAddress((void**)&p_h1l, g_h1l);
    cudaGetSymbolAddress((void**)&p_zh,  g_zh);
    cudaGetSymbolAddress((void**)&p_zl,  g_zl);
    cudaGetSymbolAddress((void**)&p_dh,  g_dh);
    cudaGetSymbolAddress((void**)&p_dl,  g_dl);
    cudaGetSymbolAddress((void**)&p_w1h, g_w1h);
    cudaGetSymbolAddress((void**)&p_w1l, g_w1l);
    cudaGetSymbolAddress((void**)&p_w2h, g_w2h);
    cudaGetSymbolAddress((void**)&p_w2l, g_w2l);
    cudaGetSymbolAddress((void**)&p_wd1h, g_wd1h);
    cudaGetSymbolAddress((void**)&p_wd1l, g_wd1l);
    cudaGetSymbolAddress((void**)&p_wd2h, g_wd2h);
    cudaGetSymbolAddress((void**)&p_wd2l, g_wd2l);

    const int STG = 2 * (128 * 72 * 2) + 2 * (64 * 72 * 2);  // 55296
    cudaFuncSetAttribute((const void*)k_gemm_bf<128, 256, true,  true,  true,  false>,
                         cudaFuncAttributeMaxDynamicSharedMemorySize, 2 * STG);
    cudaFuncSetAttribute((const void*)k_gemm_bf<256, 64,  false, false, false, true >,
                         cudaFuncAttributeMaxDynamicSharedMemorySize, 2 * STG);
    cudaFuncSetAttribute((const void*)k_gemm_bf<64,  256, true,  true,  true,  false>,
                         cudaFuncAttributeMaxDynamicSharedMemorySize, STG);
    cudaFuncSetAttribute((const void*)k_gemm_bf<256, 128, true,  false, false, false>,
                         cudaFuncAttributeMaxDynamicSharedMemorySize, 2 * STG);

    // --- prep (weight splits + deg init) + degree count
    k_prep<<<(98304 + NN + 255) / 256, 256>>>(W1, W2, Wd1, Wd2);
    k_deg_count<<<(ECNT + 255) / 256, 256>>>(dstp);

    const int MB = (NN + 127) / 128;   // 391 row-blocks

    // --- layer 1: aggx = Dsym-scatter(x); split; h1 = relu(aggx@W1+b1)
    k_init_agg<128><<<(NN * 32 + 255) / 256, 256>>>(x, p_aggx);
    k_scat1<<<ECNT / 4 / 8, 256>>>(srcp, dstp, x, p_aggx);        // 25000 blocks
    k_split<<<(NN * 32 + 255) / 256, 256>>>(p_aggx, p_axh, p_axl, NN * 32);
    k_gemm_bf<128, 256, true, true, true, false><<<dim3(4, MB), 256, 2 * STG>>>(
        p_axh, p_axl, p_w1h, p_w1l, b1, nullptr, p_h1h, p_h1l);

    // --- layer 2: h2 = h1 @ W2 [fp32, fused z-init]; scatter; split
    k_gemm_bf<256, 64, false, false, false, true><<<dim3(1, MB), 256, 2 * STG>>>(
        p_h1h, p_h1l, p_w2h, p_w2l, b2, p_h2, nullptr, nullptr);
    k_scat2<<<ECNT / 8 / 8, 256>>>(srcp, dstp, p_h2, p_z);        // 12500 blocks
    k_split<<<(NN * 16 + 255) / 256, 256>>>(p_z, p_zh, p_zl, NN * 16);

    // --- decoder: d = relu(z @ Wd1 + bd1); out = d @ Wd2 + bd2
    k_gemm_bf<64, 256, true, true, true, false><<<dim3(4, MB), 256, STG>>>(
        p_zh, p_zl, p_wd1h, p_wd1l, bd1, nullptr, p_dh, p_dl);
    k_gemm_bf<256, 128, true, false, false, false><<<dim3(2, MB), 256, 2 * STG>>>(
        p_dh, p_dl, p_wd2h, p_wd2l, bd2, out, nullptr, nullptr);
}